// round 11
// baseline (speedup 1.0000x reference)
#include <cuda_runtime.h>
#include <cuda_bf16.h>
#include <cstdint>

#define BATCH 512
#define FEAT  512
#define NBLK  128
#define NTHR  512

#define AS_STR 520                         // 512 + 8 bf16 pad
#define AS_BYTES (64 * AS_STR * 2)         // 66560
#define BS_BYTES (32 * AS_STR * 2)         // 33280
#define CS_STR 34                          // 32 + 2 pad floats
#define CS_BYTES (64 * CS_STR * 4)         // 8704
#define SMEM_TOTAL (AS_BYTES + BS_BYTES + CS_BYTES)   // 108544

__device__ float g_refs[BATCH * 8];        // refs[r][j] = S[r, 8*(r/8)+j]
__device__ float g_rkp[BATCH * 8 * 16];    // [(row*8+j)*16 + bx] partial rk sums
__device__ unsigned g_bandA[8];            // monotonic band counters
__device__ unsigned g_bandB[8];
__device__ unsigned long long g_sum = 0;
__device__ unsigned g_done = 0;

#define SUM_SCALE 1073741824.0f            // 2^30
#define INV_SUM   (1.0 / 1073741824.0)

__global__ void __launch_bounds__(NTHR, 1) fused_kernel(const float* __restrict__ fs,
                                                        const float* __restrict__ ft,
                                                        float* __restrict__ out) {
    extern __shared__ __align__(16) char smem[];
    __nv_bfloat16 (*As)[AS_STR] = (__nv_bfloat16(*)[AS_STR])smem;
    __nv_bfloat16 (*Bs)[AS_STR] = (__nv_bfloat16(*)[AS_STR])(smem + AS_BYTES);
    float (*Cs)[CS_STR]         = (float(*)[CS_STR])(smem + AS_BYTES + BS_BYTES);

    __shared__ float wrp[2][4][8][2][8];   // [wn][wm][g][rowhalf][j]
    __shared__ unsigned baseA, baseB;

    const int tid   = threadIdx.x;
    const int bx    = blockIdx.x;          // 0..15
    const int by    = blockIdx.y;          // 0..7
    const int mTile = by * 64;
    const int nTile = bx * 32;
    const int warp  = tid >> 5;
    const int lane  = tid & 31;
    const int kh    = warp >> 3;           // k-half
    const int wq    = warp & 7;
    const int wm    = wq & 3;
    const int wn    = wq >> 2;

    if (tid == 0) { baseA = g_bandA[by]; baseB = g_bandB[by]; }

    // ================= Stage A and B tiles (fp32 -> bf16) ====================
    {
        const float4* ag = (const float4*)(fs + mTile * FEAT);
        #pragma unroll 16
        for (int v = 0; v < 16; v++) {
            const int idx = tid + v * NTHR;
            const int row = idx >> 7, c4 = idx & 127;
            const float4 x = ag[row * 128 + c4];
            __nv_bfloat162 h0 = __floats2bfloat162_rn(x.x, x.y);
            __nv_bfloat162 h1 = __floats2bfloat162_rn(x.z, x.w);
            uint2 pk = make_uint2(*(uint32_t*)&h0, *(uint32_t*)&h1);
            *(uint2*)&As[row][c4 * 4] = pk;
        }
        const float4* bg = (const float4*)(ft + nTile * FEAT);
        #pragma unroll 8
        for (int v = 0; v < 8; v++) {
            const int idx = tid + v * NTHR;
            const int row = idx >> 7, c4 = idx & 127;
            const float4 x = bg[row * 128 + c4];
            __nv_bfloat162 h0 = __floats2bfloat162_rn(x.x, x.y);
            __nv_bfloat162 h1 = __floats2bfloat162_rn(x.z, x.w);
            uint2 pk = make_uint2(*(uint32_t*)&h0, *(uint32_t*)&h1);
            *(uint2*)&Bs[row][c4 * 4] = pk;
        }
    }
    __syncthreads();

    // ================= Mainloop: 16 k-steps per warp (k-half split) ==========
    float acc[2][4] = {};
    const int a_row = 16 * wm + (lane & 7) + ((lane >> 3) & 1) * 8;
    const int a_k8  = (lane >> 4) * 8;
    const int b_row = 16 * wn + (lane & 7) + (lane >> 4) * 8;
    const int b_k8  = ((lane >> 3) & 1) * 8;

    const uint32_t abase = (uint32_t)__cvta_generic_to_shared(&As[a_row][a_k8]) + kh * 512;
    const uint32_t bbase = (uint32_t)__cvta_generic_to_shared(&Bs[b_row][b_k8]) + kh * 512;

    #pragma unroll
    for (int kk = 0; kk < 16; kk++) {
        const uint32_t koff = kk * 32;
        uint32_t a0, a1, a2, a3, b0, b1, b2, b3;
        asm volatile("ldmatrix.sync.aligned.m8n8.x4.shared.b16 {%0,%1,%2,%3}, [%4];\n"
                     : "=r"(a0), "=r"(a1), "=r"(a2), "=r"(a3) : "r"(abase + koff));
        asm volatile("ldmatrix.sync.aligned.m8n8.x4.shared.b16 {%0,%1,%2,%3}, [%4];\n"
                     : "=r"(b0), "=r"(b1), "=r"(b2), "=r"(b3) : "r"(bbase + koff));
        asm volatile("mma.sync.aligned.m16n8k16.row.col.f32.bf16.bf16.f32 "
                     "{%0,%1,%2,%3}, {%4,%5,%6,%7}, {%8,%9}, {%0,%1,%2,%3};\n"
                     : "+f"(acc[0][0]), "+f"(acc[0][1]), "+f"(acc[0][2]), "+f"(acc[0][3])
                     : "r"(a0), "r"(a1), "r"(a2), "r"(a3), "r"(b0), "r"(b1));
        asm volatile("mma.sync.aligned.m16n8k16.row.col.f32.bf16.bf16.f32 "
                     "{%0,%1,%2,%3}, {%4,%5,%6,%7}, {%8,%9}, {%0,%1,%2,%3};\n"
                     : "+f"(acc[1][0]), "+f"(acc[1][1]), "+f"(acc[1][2]), "+f"(acc[1][3])
                     : "r"(a0), "r"(a1), "r"(a2), "r"(a3), "r"(b2), "r"(b3));
    }

    // ================= Combine k-halves in smem; kh0 holds full S ============
    const int g = lane >> 2, t = lane & 3;
    if (kh == 1) {
        #pragma unroll
        for (int h = 0; h < 2; h++) {
            *(float2*)&Cs[16 * wm + g][16 * wn + 2 * t + 8 * h] =
                make_float2(acc[h][0], acc[h][1]);
            *(float2*)&Cs[16 * wm + g + 8][16 * wn + 2 * t + 8 * h] =
                make_float2(acc[h][2], acc[h][3]);
        }
    }
    __syncthreads();

    float S[2][4];
    if (kh == 0) {
        #pragma unroll
        for (int h = 0; h < 2; h++) {
            const float2 u0 = *(float2*)&Cs[16 * wm + g][16 * wn + 2 * t + 8 * h];
            const float2 u1 = *(float2*)&Cs[16 * wm + g + 8][16 * wn + 2 * t + 8 * h];
            S[h][0] = acc[h][0] + u0.x;  S[h][1] = acc[h][1] + u0.y;
            S[h][2] = acc[h][2] + u1.x;  S[h][3] = acc[h][3] + u1.y;
        }
        // Diagonal warps publish refs: rows r0 use h=0 (j=2t,2t+1), rows r0+8 use h=1
        if (nTile + 16 * wn == mTile + 16 * wm) {
            const int r0 = mTile + 16 * wm + g;
            *(float2*)&g_refs[r0 * 8 + 2 * t]       = make_float2(S[0][0], S[0][1]);
            *(float2*)&g_refs[(r0 + 8) * 8 + 2 * t] = make_float2(S[1][2], S[1][3]);
        }
    }

    // ================= Band barrier A: refs visible ==========================
    __syncthreads();
    if (tid == 0) {
        __threadfence();
        atomicAdd(&g_bandA[by], 1u);
        const unsigned target = baseA + 16u;
        while ((int)(*(volatile unsigned*)&g_bandA[by] - target) < 0) {}
        __threadfence();
    }
    __syncthreads();

    // ================= Partial rk from registers (kh0 warps) =================
    if (kh == 0) {
        const int r0 = mTile + 16 * wm + g;
        const int r1 = r0 + 8;
        float rf0[8], rf1[8];
        *(float4*)&rf0[0] = __ldcg((const float4*)&g_refs[r0 * 8]);
        *(float4*)&rf0[4] = __ldcg((const float4*)&g_refs[r0 * 8 + 4]);
        *(float4*)&rf1[0] = __ldcg((const float4*)&g_refs[r1 * 8]);
        *(float4*)&rf1[4] = __ldcg((const float4*)&g_refs[r1 * 8 + 4]);

        float p0[8], p1[8];
        #pragma unroll
        for (int j = 0; j < 8; j++) {
            p0[j] = fmaxf(S[0][0] - rf0[j], 0.f) + fmaxf(S[0][1] - rf0[j], 0.f)
                  + fmaxf(S[1][0] - rf0[j], 0.f) + fmaxf(S[1][1] - rf0[j], 0.f);
            p1[j] = fmaxf(S[0][2] - rf1[j], 0.f) + fmaxf(S[0][3] - rf1[j], 0.f)
                  + fmaxf(S[1][2] - rf1[j], 0.f) + fmaxf(S[1][3] - rf1[j], 0.f);
        }
        #pragma unroll
        for (int o = 1; o <= 2; o <<= 1) {
            #pragma unroll
            for (int j = 0; j < 8; j++) {
                p0[j] += __shfl_down_sync(0xffffffffu, p0[j], o);
                p1[j] += __shfl_down_sync(0xffffffffu, p1[j], o);
            }
        }
        if (t == 0) {
            #pragma unroll
            for (int j = 0; j < 8; j++) {
                wrp[wn][wm][g][0][j] = p0[j];
                wrp[wn][wm][g][1][j] = p1[j];
            }
        }
    }
    __syncthreads();

    // ================= Write per-CTA rk partials (512 entries) ===============
    {
        const int lr = tid >> 3;           // local row 0..63
        const int j  = tid & 7;
        const int ewm = lr >> 4, eg = lr & 7, erh = (lr >> 3) & 1;
        const float val = wrp[0][ewm][eg][erh][j] + wrp[1][ewm][eg][erh][j];
        g_rkp[((mTile + lr) * 8 + j) * 16 + bx] = val;
    }

    // ================= Band barrier B: rkp visible ===========================
    __syncthreads();
    if (tid == 0) {
        __threadfence();
        atomicAdd(&g_bandB[by], 1u);
        const unsigned target = baseB + 16u;
        while ((int)(*(volatile unsigned*)&g_bandB[by] - target) < 0) {}
        __threadfence();
    }
    __syncthreads();

    // ================= Ratios for rows mTile + bx*4 .. +3 ====================
    float ratio = 0.f;
    if (tid < 32) {
        const int rl = tid >> 3, j = tid & 7;
        const int r  = mTile + bx * 4 + rl;
        float rf[8];
        *(float4*)&rf[0] = __ldcg((const float4*)&g_refs[r * 8]);
        *(float4*)&rf[4] = __ldcg((const float4*)&g_refs[r * 8 + 4]);
        const float4* q = (const float4*)&g_rkp[(r * 8 + j) * 16];
        const float4 qa = __ldcg(q), qb = __ldcg(q + 1), qc = __ldcg(q + 2), qd = __ldcg(q + 3);
        float rk = 1.f;
        rk += qa.x; rk += qa.y; rk += qa.z; rk += qa.w;
        rk += qb.x; rk += qb.y; rk += qb.z; rk += qb.w;
        rk += qc.x; rk += qc.y; rk += qc.z; rk += qc.w;
        rk += qd.x; rk += qd.y; rk += qd.z; rk += qd.w;
        const float pj = rf[j];
        float ps = 0.f;
        #pragma unroll
        for (int k = 0; k < 8; k++) ps += fmaxf(rf[k] - pj, 0.f);
        ratio = (1.f + ps) / rk;
        #pragma unroll
        for (int o = 16; o > 0; o >>= 1)
            ratio += __shfl_down_sync(0xffffffffu, ratio, o);
    }

    // ================= Deterministic fixed-point tail ========================
    if (tid == 0) {
        atomicAdd(&g_sum, (unsigned long long)llrintf(ratio * SUM_SCALE));
        __threadfence();
        const unsigned prev = atomicAdd(&g_done, 1);
        if (prev == NBLK - 1) {
            const unsigned long long tot = *((volatile unsigned long long*)&g_sum);
            out[0] = (float)(1.0 - ((double)tot * INV_SUM) * (1.0 / 4096.0));
            g_sum  = 0;
            g_done = 0;
        }
    }
}

extern "C" void kernel_launch(void* const* d_in, const int* in_sizes, int n_in,
                              void* d_out, int out_size) {
    const float* fs = (const float*)d_in[0];
    const float* ft = (const float*)d_in[1];
    float* out = (float*)d_out;

    cudaFuncSetAttribute(fused_kernel,
                         cudaFuncAttributeMaxDynamicSharedMemorySize, SMEM_TOTAL);
    fused_kernel<<<dim3(16, 8), NTHR, SMEM_TOTAL>>>(fs, ft, out);
}

// round 12
// speedup vs baseline: 1.1629x; 1.1629x over previous
#include <cuda_runtime.h>
#include <cuda_bf16.h>
#include <cstdint>

#define BATCH 512
#define FEAT  512
#define NBLK  128
#define NTHR  512

#define KH_LEN 256                          // K per CTA (half)
#define AS_STR 264                          // 256 + 8 bf16 pad (528B row ≡ 1 mod 32 banks)
#define A_BYTES (64 * AS_STR * 2)           // 33792
#define B_BYTES (64 * AS_STR * 2)           // 33792
#define SMEM_TOTAL (A_BYTES + B_BYTES)      // 67584

__device__ float g_S0[BATCH * BATCH];       // k in [0,256) partial S
__device__ float g_S1[BATCH * BATCH];       // k in [256,512) partial S
__device__ unsigned g_band[8];              // monotonic band counters
__device__ unsigned long long g_sum = 0;
__device__ unsigned g_done = 0;

#define SUM_SCALE 1073741824.0f             // 2^30
#define INV_SUM   (1.0 / 1073741824.0)

__global__ void __launch_bounds__(NTHR, 1) fused_kernel(const float* __restrict__ fs,
                                                        const float* __restrict__ ft,
                                                        float* __restrict__ out) {
    extern __shared__ __align__(16) char smem[];
    __nv_bfloat16 (*As)[AS_STR] = (__nv_bfloat16(*)[AS_STR])smem;
    __nv_bfloat16 (*Bs)[AS_STR] = (__nv_bfloat16(*)[AS_STR])(smem + A_BYTES);

    __shared__ float refs[4][8];
    __shared__ float wr[16][8];
    __shared__ unsigned band_base;

    const int tid   = threadIdx.x;
    const int bx    = blockIdx.x;           // 0..7 (nTile)
    const int by    = blockIdx.y;           // 0..7 (mTile band)
    const int kh    = blockIdx.z;           // 0..1 (K half)
    const int mTile = by * 64;
    const int nTile = bx * 64;
    const int kOff  = kh * KH_LEN;
    const int warp  = tid >> 5;
    const int lane  = tid & 31;
    const int wm    = warp & 3;              // 4x4 warp grid over 64x64 tile
    const int wn    = warp >> 2;

    if (tid == 0) band_base = g_band[by];

    // ================= Stage A and B tiles (fp32 -> bf16) ====================
    // 64 rows x 256 cols each = 4096 float4 chunks; 8 per thread per tensor.
    {
        #pragma unroll 8
        for (int v = 0; v < 8; v++) {
            const int idx = tid + v * NTHR;
            const int row = idx >> 6;        // 0..63
            const int c4  = idx & 63;        // 0..63 float4 chunks (256 floats)
            const float4 x = *(const float4*)(fs + (mTile + row) * FEAT + kOff + c4 * 4);
            __nv_bfloat162 h0 = __floats2bfloat162_rn(x.x, x.y);
            __nv_bfloat162 h1 = __floats2bfloat162_rn(x.z, x.w);
            uint2 pk = make_uint2(*(uint32_t*)&h0, *(uint32_t*)&h1);
            *(uint2*)&As[row][c4 * 4] = pk;
        }
        #pragma unroll 8
        for (int v = 0; v < 8; v++) {
            const int idx = tid + v * NTHR;
            const int row = idx >> 6;
            const int c4  = idx & 63;
            const float4 x = *(const float4*)(ft + (nTile + row) * FEAT + kOff + c4 * 4);
            __nv_bfloat162 h0 = __floats2bfloat162_rn(x.x, x.y);
            __nv_bfloat162 h1 = __floats2bfloat162_rn(x.z, x.w);
            uint2 pk = make_uint2(*(uint32_t*)&h0, *(uint32_t*)&h1);
            *(uint2*)&Bs[row][c4 * 4] = pk;
        }
    }
    __syncthreads();

    // ================= Mainloop: 16 k16-steps per warp =======================
    float acc[2][4] = {};
    const int a_row = 16 * wm + (lane & 7) + ((lane >> 3) & 1) * 8;
    const int a_k8  = (lane >> 4) * 8;
    const int b_row = 16 * wn + (lane & 7) + (lane >> 4) * 8;
    const int b_k8  = ((lane >> 3) & 1) * 8;

    const uint32_t abase = (uint32_t)__cvta_generic_to_shared(&As[a_row][a_k8]);
    const uint32_t bbase = (uint32_t)__cvta_generic_to_shared(&Bs[b_row][b_k8]);

    #pragma unroll
    for (int kk = 0; kk < 16; kk++) {
        const uint32_t koff = kk * 32;       // 16 bf16 = 32 bytes per step
        uint32_t a0, a1, a2, a3, b0, b1, b2, b3;
        asm volatile("ldmatrix.sync.aligned.m8n8.x4.shared.b16 {%0,%1,%2,%3}, [%4];\n"
                     : "=r"(a0), "=r"(a1), "=r"(a2), "=r"(a3) : "r"(abase + koff));
        asm volatile("ldmatrix.sync.aligned.m8n8.x4.shared.b16 {%0,%1,%2,%3}, [%4];\n"
                     : "=r"(b0), "=r"(b1), "=r"(b2), "=r"(b3) : "r"(bbase + koff));
        asm volatile("mma.sync.aligned.m16n8k16.row.col.f32.bf16.bf16.f32 "
                     "{%0,%1,%2,%3}, {%4,%5,%6,%7}, {%8,%9}, {%0,%1,%2,%3};\n"
                     : "+f"(acc[0][0]), "+f"(acc[0][1]), "+f"(acc[0][2]), "+f"(acc[0][3])
                     : "r"(a0), "r"(a1), "r"(a2), "r"(a3), "r"(b0), "r"(b1));
        asm volatile("mma.sync.aligned.m16n8k16.row.col.f32.bf16.bf16.f32 "
                     "{%0,%1,%2,%3}, {%4,%5,%6,%7}, {%8,%9}, {%0,%1,%2,%3};\n"
                     : "+f"(acc[1][0]), "+f"(acc[1][1]), "+f"(acc[1][2]), "+f"(acc[1][3])
                     : "r"(a0), "r"(a1), "r"(a2), "r"(a3), "r"(b2), "r"(b3));
    }

    // ================= Epilogue: STG partial S to this K-half's buffer =======
    {
        const int g = lane >> 2, t = lane & 3;
        const int row0 = mTile + 16 * wm + g;
        float* dst = kh ? g_S1 : g_S0;
        #pragma unroll
        for (int h = 0; h < 2; h++) {
            const int col = nTile + 16 * wn + t * 2 + 8 * h;
            *(float2*)&dst[row0 * BATCH + col]       = make_float2(acc[h][0], acc[h][1]);
            *(float2*)&dst[(row0 + 8) * BATCH + col] = make_float2(acc[h][2], acc[h][3]);
        }
    }
    __syncthreads();

    // ================= Band-local barrier (16 CTAs: 8 bx x 2 kh) =============
    if (tid == 0) {
        __threadfence();
        atomicAdd(&g_band[by], 1u);
        const unsigned target = band_base + 16u;
        while ((int)(*(volatile unsigned*)&g_band[by] - target) < 0) {}
        __threadfence();
    }
    __syncthreads();

    // ================= Phase 2: 4 rows per CTA, 128 thr/row ==================
    const int row_l = tid >> 7;              // 0..3
    const int c     = tid & 127;             // float4 chunk of the 512-wide row
    const int r     = by * 64 + (kh * 8 + bx) * 4 + row_l;
    const float4 u0 = ((const float4*)(g_S0 + r * BATCH))[c];
    const float4 u1 = ((const float4*)(g_S1 + r * BATCH))[c];
    const float4 v  = make_float4(u0.x + u1.x, u0.y + u1.y, u0.z + u1.z, u0.w + u1.w);

    const int rc0 = (r & ~7) >> 2;
    if (c == rc0)     *(float4*)&refs[row_l][0] = v;
    if (c == rc0 + 1) *(float4*)&refs[row_l][4] = v;
    __syncthreads();

    float p[8];
    #pragma unroll
    for (int j = 0; j < 8; j++) p[j] = refs[row_l][j];

    float s8[8];
    #pragma unroll
    for (int j = 0; j < 8; j++) {
        s8[j] = fmaxf(v.x - p[j], 0.f) + fmaxf(v.y - p[j], 0.f)
              + fmaxf(v.z - p[j], 0.f) + fmaxf(v.w - p[j], 0.f);
    }
    #pragma unroll
    for (int o = 16; o > 0; o >>= 1)
        #pragma unroll
        for (int j = 0; j < 8; j++)
            s8[j] += __shfl_down_sync(0xffffffffu, s8[j], o);
    if (lane == 0) {
        #pragma unroll
        for (int j = 0; j < 8; j++) wr[warp][j] = s8[j];
    }
    __syncthreads();

    float ratio = 0.f;
    if (tid < 32) {
        const int rl = tid >> 3, j = tid & 7;
        const float rk = 1.f + wr[rl * 4][j] + wr[rl * 4 + 1][j]
                             + wr[rl * 4 + 2][j] + wr[rl * 4 + 3][j];
        const float pj = refs[rl][j];
        float ps = 0.f;
        #pragma unroll
        for (int k = 0; k < 8; k++) ps += fmaxf(refs[rl][k] - pj, 0.f);
        ratio = (1.f + ps) / rk;
        #pragma unroll
        for (int o = 16; o > 0; o >>= 1)
            ratio += __shfl_down_sync(0xffffffffu, ratio, o);
    }

    // ================= Deterministic fixed-point tail ========================
    if (tid == 0) {
        atomicAdd(&g_sum, (unsigned long long)llrintf(ratio * SUM_SCALE));
        __threadfence();
        const unsigned prev = atomicAdd(&g_done, 1);
        if (prev == NBLK - 1) {
            const unsigned long long tot = *((volatile unsigned long long*)&g_sum);
            out[0] = (float)(1.0 - ((double)tot * INV_SUM) * (1.0 / 4096.0));
            g_sum  = 0;
            g_done = 0;
        }
    }
}

extern "C" void kernel_launch(void* const* d_in, const int* in_sizes, int n_in,
                              void* d_out, int out_size) {
    const float* fs = (const float*)d_in[0];
    const float* ft = (const float*)d_in[1];
    float* out = (float*)d_out;

    cudaFuncSetAttribute(fused_kernel,
                         cudaFuncAttributeMaxDynamicSharedMemorySize, SMEM_TOTAL);
    fused_kernel<<<dim3(8, 8, 2), NTHR, SMEM_TOTAL>>>(fs, ft, out);
}